// round 8
// baseline (speedup 1.0000x reference)
#include <cuda_runtime.h>

#define NB 64
#define NS 256
#define NI 256
#define NHH 512
#define N2H 1024
#define NM (NB*NS)

// Scratch for the pre-activation GEMM output i = x @ W^T   [16384 x 1024], 64MB
static __device__ float g_C[(size_t)NM * N2H];

typedef unsigned long long u64;
__device__ __forceinline__ u64 pk2(float lo, float hi){ u64 r; asm("mov.b64 %0,{%1,%2};" : "=l"(r) : "f"(lo), "f"(hi)); return r; }
__device__ __forceinline__ void up2(u64 a, float& lo, float& hi){ asm("mov.b64 {%0,%1},%2;" : "=f"(lo), "=f"(hi) : "l"(a)); }
__device__ __forceinline__ u64 fma2(u64 a, u64 b, u64 c){ u64 d; asm("fma.rn.f32x2 %0,%1,%2,%3;" : "=l"(d) : "l"(a), "l"(b), "l"(c)); return d; }
__device__ __forceinline__ u64 mul2(u64 a, u64 b){ u64 d; asm("mul.rn.f32x2 %0,%1,%2;" : "=l"(d) : "l"(a), "l"(b)); return d; }
__device__ __forceinline__ u64 add2(u64 a, u64 b){ u64 d; asm("add.rn.f32x2 %0,%1,%2;" : "=l"(d) : "l"(a), "l"(b)); return d; }

// Exact-ish tanh for the trace kernel (rel err ~1e-6).
__device__ __forceinline__ float fast_tanh(float x){
    float z = __expf(2.0f * x);
    return 1.0f - __fdividef(2.0f, z + 1.0f);
}
// Single-instruction MUFU.TANH (sm_75+), rel err ~1.6e-5.
__device__ __forceinline__ float tanh_approx(float x){
    float r; asm("tanh.approx.f32 %0, %1;" : "=f"(r) : "f"(x)); return r;
}

union F4U { float4 f; u64 u[2]; };

// ---------------------------------------------------------------------------
// Kernel 1: SGEMM  C[m][n] = sum_k x[m][k] * W[n][k]
// 128x128 tile, BK=32, 256 thd, 8x8 per thread, inner loop in fma.rn.f32x2.
// __launch_bounds__(256,2) FORCES regs<=128 so 2 blocks/SM stay resident
// (measured R6: at 135 regs occupancy halves and the f32x2 win evaporates).
// ---------------------------------------------------------------------------
#define BM 128
#define BN 128
#define BK 32

__global__ __launch_bounds__(256, 2) void sgemm_kernel(const float* __restrict__ A,
                                                       const float* __restrict__ W)
{
    __shared__ float As[BK][BM+4];
    __shared__ float Bs[BK][BN+4];
    const int tid = threadIdx.x;
    const int m0 = blockIdx.y * BM;
    const int n0 = blockIdx.x * BN;
    const int tr = tid >> 4;        // 0..15
    const int tc = tid & 15;        // 0..15

    u64 acc2[8][4];                 // [i][j-pair], 8 rows x 8 cols packed
    #pragma unroll
    for (int i=0;i<8;i++)
        #pragma unroll
        for (int j=0;j<4;j++) acc2[i][j]=0ULL;

    const int lr = tid >> 3;          // 0..31
    const int lc = (tid & 7) << 2;    // 0,4,...,28

    for (int k0=0; k0<NI; k0+=BK){
        #pragma unroll
        for (int h=0; h<4; h++){
            int r = lr + h*32;
            float4 av = *(const float4*)(A + (size_t)(m0+r)*NI + k0 + lc);
            As[lc+0][r]=av.x; As[lc+1][r]=av.y; As[lc+2][r]=av.z; As[lc+3][r]=av.w;
            float4 bv = *(const float4*)(W + (size_t)(n0+r)*NI + k0 + lc);
            Bs[lc+0][r]=bv.x; Bs[lc+1][r]=bv.y; Bs[lc+2][r]=bv.z; Bs[lc+3][r]=bv.w;
        }
        __syncthreads();
        #pragma unroll
        for (int kk=0;kk<BK;kk++){
            float a[8];
            u64 bb2[4];
            *(float4*)(a)    = *(const float4*)(&As[kk][tr*8]);
            *(float4*)(a+4)  = *(const float4*)(&As[kk][tr*8+4]);
            { F4U b; b.f = *(const float4*)(&Bs[kk][tc*8]);   bb2[0]=b.u[0]; bb2[1]=b.u[1]; }
            { F4U b; b.f = *(const float4*)(&Bs[kk][tc*8+4]); bb2[2]=b.u[0]; bb2[3]=b.u[1]; }
            #pragma unroll
            for (int i=0;i<8;i++){
                u64 a2 = pk2(a[i], a[i]);
                #pragma unroll
                for (int j=0;j<4;j++)
                    acc2[i][j] = fma2(a2, bb2[j], acc2[i][j]);
            }
        }
        __syncthreads();
    }
    #pragma unroll
    for (int i=0;i<8;i++){
        float* cptr = g_C + (size_t)(m0 + tr*8 + i)*N2H + n0 + tc*8;
        F4U u0; u0.u[0]=acc2[i][0]; u0.u[1]=acc2[i][1];
        F4U u1; u1.u[0]=acc2[i][2]; u1.u[1]=acc2[i][3];
        *(float4*)(cptr)   = u0.f;
        *(float4*)(cptr+4) = u1.f;
    }
}

// ---------------------------------------------------------------------------
// Kernel 2: k-trace precompute.
// ---------------------------------------------------------------------------
__global__ __launch_bounds__(256) void trace_kernel(float* __restrict__ keys_out)
{
    int gid = blockIdx.x*blockDim.x + threadIdx.x;   // 0..32767
    int b = gid >> 9;
    int h = gid & 511;
    const float* c = g_C + (size_t)b*NS*N2H + h;      // ik column
    float* ko = keys_out + (size_t)b*NS*NHH + h;
    const float ALPHA = 0.9048374180359595f;
    float ks = 0.f;
    #pragma unroll 8
    for (int t=0;t<NS;t++){
        ks = fmaf(ks, ALPHA, __ldg(c + (size_t)t*N2H));
        ko[(size_t)t*NHH] = fast_tanh(ks);
    }
}

// ---------------------------------------------------------------------------
// Kernel 3: main recurrence, LOOKAHEAD-PIPELINED.
//   dot_t = pd + w_{t-1}*gk,  pd = m''_{t-1}.k_t (pre-w_{t-1}... see below),
// with per-iteration order  B(mem+=kt'_{t-1} w_{t-1}) -> C(kt'+=k_t) ->
// A(scalar chain) -> sync -> E(lookahead dots vs k_{t+1} + butterfly).
// B,C are ~100 cyc of fma2 issued between the butterfly (end of prev iter)
// and its consumer A -> reduce latency hidden. E is independent of A.
// k_t staged via double-buffered smem, one cooperative 2KB store per step.
// One warp owns 4 scaled mem rows (m''=mem/P) in registers.
// ---------------------------------------------------------------------------
__global__ __launch_bounds__(128, 3) void recur_kernel(const float* __restrict__ keys,
                                                       float* __restrict__ mem_out,
                                                       float* __restrict__ vals_out)
{
    __shared__ float sk[2][NHH];

    const int b    = blockIdx.y;
    const int rg   = blockIdx.x;       // 0..31
    const int tid  = threadIdx.x;
    const int warp = tid >> 5;         // 0..3
    const int lane = tid & 31;
    const int row0 = rg*16 + warp*4;

    const float ALPHA = 0.9048374180359595f;   // exp(-1/10)
    const float DEC   = 0.9512294245007140f;   // exp(-1/20)
    const float OMD   = 0.0487705754992860f;   // 1 - DEC
    const float LR    = 0.01f;

    u64 m[4][8], kt[8], kp[8];
    #pragma unroll
    for (int r=0;r<4;r++)
        #pragma unroll
        for (int p=0;p<8;p++) m[r][p]=0ULL;
    #pragma unroll
    for (int p=0;p<8;p++) kt[p]=0ULL;

    // packed per-row scalar state: (row0,row1) and (row2,row3)
    u64 vs01=0ULL, vs23=0ULL, vt01=0ULL, vt23=0ULL;
    u64 P01 = pk2(1.f,1.f),        P23 = pk2(1.f,1.f);
    u64 Q01 = pk2(LR*OMD, LR*OMD), Q23 = Q01;
    u64 pd01=0ULL, pd23=0ULL;      // lookahead raw dots m''.k_t
    u64 gk2 = 0ULL;                // (gk,gk)
    u64 w01p=0ULL, w23p=0ULL;      // w''_{t-1}

    const u64 ONE2   = pk2(1.f, 1.f);
    const u64 NEG2   = pk2(-1.f, -1.f);
    const u64 A2     = pk2(ALPHA, ALPHA);
    const u64 DEC2   = pk2(DEC, DEC);
    const u64 OMD2   = pk2(OMD, OMD);
    const u64 LR2    = pk2(LR, LR);
    const u64 K02    = pk2(0.2f, 0.2f);

    const float* kg   = keys + (size_t)b*NS*NHH;            // global keys, batch b
    const float4* ivb = (const float4*)(g_C + (size_t)b*NS*N2H + NHH + row0);
    float4*       vb  = (float4*)(vals_out + (size_t)b*NS*NHH + row0);

    // init: kp = k_0 (direct global), knext = k_1 slice, iv_0
    #pragma unroll
    for (int c=0;c<4;c++){
        F4U kv; kv.f = __ldg((const float4*)(kg) + c*32 + lane);
        kp[2*c]=kv.u[0]; kp[2*c+1]=kv.u[1];
    }
    float4 knext = *(const float4*)(kg + (size_t)1*NHH + tid*4);
    float4 ivf = __ldg(&ivb[0]);

    for (int t=0;t<NS;t++){
        const int buf = t & 1;

        // ---- B: apply previous rank-1 update m'' += kt'_{t-1} * w_{t-1} ----
        {
            float a0,a1,a2,a3;
            up2(w01p,a0,a1); up2(w23p,a2,a3);
            u64 wp0=pk2(a0,a0), wp1=pk2(a1,a1), wp2=pk2(a2,a2), wp3=pk2(a3,a3);
            #pragma unroll
            for (int p=0;p<8;p++){
                m[0][p] = fma2(kt[p], wp0, m[0][p]);
                m[1][p] = fma2(kt[p], wp1, m[1][p]);
                m[2][p] = fma2(kt[p], wp2, m[2][p]);
                m[3][p] = fma2(kt[p], wp3, m[3][p]);
            }
        }

        // ---- C: kt' update with k_t (kp) ----
        #pragma unroll
        for (int p=0;p<8;p++) kt[p] = fma2(kt[p], DEC2, kp[p]);

        // stage k_{t+1} into smem; issue next global loads
        *(float4*)(&sk[buf][tid*4]) = knext;
        if (t+2 < NS) knext = *(const float4*)(kg + (size_t)(t+2)*NHH + tid*4);
        float4 ivn = __ldg(&ivb[(size_t)((t+1<NS)?(t+1):t)*(N2H/4)]);

        // ---- A: dot_t reconstruction + packed scalar chain ----
        u64 dot01 = fma2(w01p, gk2, pd01);
        u64 dot23 = fma2(w23p, gk2, pd23);
        u64 iv01 = pk2(ivf.x, ivf.y);
        u64 iv23 = pk2(ivf.z, ivf.w);
        u64 d01 = mul2(dot01, P01);
        u64 d23 = mul2(dot23, P23);
        vs01 = fma2(vs01, A2, fma2(K02, d01, iv01));
        vs23 = fma2(vs23, A2, fma2(K02, d23, iv23));
        float v0,v1,v2,v3;
        { float s0,s1; up2(vs01,s0,s1); v0=tanh_approx(s0); v1=tanh_approx(s1); }
        { float s2,s3; up2(vs23,s2,s3); v2=tanh_approx(s2); v3=tanh_approx(s3); }
        u64 v01 = pk2(v0,v1), v23 = pk2(v2,v3);
        vt01 = fma2(v01, OMD2, mul2(vt01, DEC2));
        vt23 = fma2(v23, OMD2, mul2(vt23, DEC2));
        u64 e01 = mul2(mul2(vt01, vt01), LR2);
        u64 e23 = mul2(mul2(vt23, vt23), LR2);
        P01 = mul2(P01, fma2(e01, NEG2, ONE2));
        P23 = mul2(P23, fma2(e23, NEG2, ONE2));
        // 1/(1-e) ~= 1+e+e^2+e^3  (err ~ e^4 <= 1e-8)
        Q01 = mul2(Q01, fma2(e01, fma2(e01, add2(ONE2, e01), ONE2), ONE2));
        Q23 = mul2(Q23, fma2(e23, fma2(e23, add2(ONE2, e23), ONE2), ONE2));
        u64 w01 = mul2(Q01, vt01);       // w_t
        u64 w23 = mul2(Q23, vt23);

        if (lane == 0)
            vb[(size_t)t*(NHH/4)] = make_float4(v0, v1, v2, v3);

        __syncthreads();   // k_{t+1} staged by all warps

        // ---- E: load k_{t+1}, lookahead dots + butterfly (indep of A) ----
        #pragma unroll
        for (int c=0;c<4;c++){
            F4U kv; kv.f = *(const float4*)(&sk[buf][c*128 + lane*4]);
            kp[2*c]=kv.u[0]; kp[2*c+1]=kv.u[1];
        }
        u64 a[4], g0=0ULL, g1=0ULL;
        #pragma unroll
        for (int r=0;r<4;r++){
            u64 s0=0ULL, s1=0ULL;
            #pragma unroll
            for (int p=0;p<8;p+=2){
                s0 = fma2(m[r][p],   kp[p],   s0);
                s1 = fma2(m[r][p+1], kp[p+1], s1);
            }
            a[r] = add2(s0, s1);
        }
        #pragma unroll
        for (int p=0;p<8;p+=2){
            g0 = fma2(kt[p],   kp[p],   g0);
            g1 = fma2(kt[p+1], kp[p+1], g1);
        }
        u64 ag = add2(g0, g1);
        float x,y;
        up2(a[0],x,y); float h0 = x+y;
        up2(a[1],x,y); float h1 = x+y;
        up2(a[2],x,y); float h2 = x+y;
        up2(a[3],x,y); float h3 = x+y;
        up2(ag,  x,y); float hg = x+y;
        u64 r01 = pk2(h0,h1), r23 = pk2(h2,h3), rg2 = pk2(hg,hg);
        #pragma unroll
        for (int o=16;o;o>>=1){
            r01 = add2(r01, __shfl_xor_sync(0xffffffffu, r01, o));
            r23 = add2(r23, __shfl_xor_sync(0xffffffffu, r23, o));
            rg2 = add2(rg2, __shfl_xor_sync(0xffffffffu, rg2, o));
        }
        pd01 = r01; pd23 = r23; gk2 = rg2;

        // rotate
        w01p = w01; w23p = w23;
        ivf = ivn;
    }

    // final pending rank-1 update: m'' += kt'_{NS-1} * w_{NS-1}
    {
        float a0,a1,a2,a3;
        up2(w01p,a0,a1); up2(w23p,a2,a3);
        u64 wp0=pk2(a0,a0), wp1=pk2(a1,a1), wp2=pk2(a2,a2), wp3=pk2(a3,a3);
        #pragma unroll
        for (int p=0;p<8;p++){
            m[0][p] = fma2(kt[p], wp0, m[0][p]);
            m[1][p] = fma2(kt[p], wp1, m[1][p]);
            m[2][p] = fma2(kt[p], wp2, m[2][p]);
            m[3][p] = fma2(kt[p], wp3, m[3][p]);
        }
    }

    // write final mem rows: mem = P_r * m''_r
    float Pf[4];
    up2(P01, Pf[0], Pf[1]); up2(P23, Pf[2], Pf[3]);
    #pragma unroll
    for (int r=0;r<4;r++){
        u64 Pp = pk2(Pf[r], Pf[r]);
        float* mo = mem_out + ((size_t)b*NHH + row0 + r)*NHH + lane*4;
        #pragma unroll
        for (int c=0;c<4;c++){
            F4U u;
            u.u[0] = mul2(m[r][2*c],   Pp);
            u.u[1] = mul2(m[r][2*c+1], Pp);
            *(float4*)(mo + c*128) = u.f;
        }
    }
}

// ---------------------------------------------------------------------------
extern "C" void kernel_launch(void* const* d_in, const int* in_sizes, int n_in,
                              void* d_out, int out_size)
{
    const float* x = (const float*)d_in[0];   // [64,256,256]
    const float* W = (const float*)d_in[1];   // [1024,256]
    float* out = (float*)d_out;
    float* mem_out  = out;                                    // [64,512,512]
    float* keys_out = out + (size_t)NB*NHH*NHH;               // [64,256,512]
    float* vals_out = keys_out + (size_t)NB*NS*NHH;           // [64,256,512]

    dim3 g1(N2H/BN, NM/BM);                 // (8, 128)
    sgemm_kernel<<<g1, 256>>>(x, W);
    trace_kernel<<<(NB*NHH)/256, 256>>>(keys_out);
    recur_kernel<<<dim3(32, NB), 128>>>(keys_out, mem_out, vals_out);
}